// round 6
// baseline (speedup 1.0000x reference)
#include <cuda_runtime.h>
#include <math.h>

#define NPTS 3072
#define NOUT 16
#define TI 32            // i-rows per block
#define TJ 256           // j-cols per block (= blockDim.x)
#define NCHUNK 8
#define ROWS_PER (NPTS / NCHUNK)            // 384 i-rows per chunk

// Sparse fill for one row-slab: warp-ballot compaction, 16-lane-per-edge writes.
// Bulk zeros come from the per-chunk cudaMemsetAsync running ahead of us.
__global__ __launch_bounds__(256) void sparse_fill_kernel(
    const float* __restrict__ coord,
    const float* __restrict__ sig,
    float* __restrict__ out,
    int i_off)
{
    __shared__ float4 s_i[TI];          // xi, yi, zi, sqi
    __shared__ float  s_inv[NOUT];      // 1/(2*sigma_c^2), reference rounding
    __shared__ float  s_qden, s_lo, s_hi;

    const int tid    = threadIdx.x;
    const int lane   = tid & 31;
    const int j_base = blockIdx.x * TJ;
    const int i_base = i_off + blockIdx.y * TI;
    const int j      = j_base + tid;
    const int jw     = j_base + (tid & ~31);   // warp's j origin

    if (tid < NOUT) {
        float s = sig[tid];
        s_inv[tid] = __fdiv_rn(1.0f, __fmul_rn(__fmul_rn(2.0f, s), s));
    }
    if (tid == 0) {
        float sm = sig[NOUT - 1];
        float qd = __fmul_rn(__fmul_rn(2.0f, sm), sm);
        s_qden = qd;
        s_lo = 0.105300f * qd;   // conservative fast-keep bound
        s_hi = 0.105420f * qd;   // conservative fast-drop bound
    }
    if (tid < TI) {
        int ig = i_base + tid;
        float x = coord[3 * ig + 0];
        float y = coord[3 * ig + 1];
        float z = coord[3 * ig + 2];
        float sq = __fadd_rn(__fadd_rn(__fmul_rn(x, x), __fmul_rn(y, y)),
                             __fmul_rn(z, z));
        s_i[tid] = make_float4(x, y, z, sq);
    }

    // j-coords register-resident across the whole i-loop
    const float xj = coord[3 * j + 0];
    const float yj = coord[3 * j + 1];
    const float zj = coord[3 * j + 2];
    const float sqj = __fadd_rn(__fadd_rn(__fmul_rn(xj, xj), __fmul_rn(yj, yj)),
                                __fmul_rn(zj, zj));
    __syncthreads();

    const float lo = s_lo, hi = s_hi, qden = s_qden;
    const int   c    = lane & (NOUT - 1);      // my output channel
    const float invc = s_inv[c];

    for (int ii = 0; ii < TI; ii++) {
        const float4 I = s_i[ii];
        const float dot = __fmaf_rn(I.z, zj, __fmaf_rn(I.y, yj, __fmul_rn(I.x, xj)));
        float d2 = __fsub_rn(__fadd_rn(I.w, sqj), __fmul_rn(2.0f, dot));
        d2 = fmaxf(d2, 0.0f);

        bool keep;
        if (d2 <= lo) {
            keep = (d2 > 0.0f) && ((i_base + ii) != j);
        } else if (d2 >= hi) {
            keep = false;
        } else {
            // boundary band: reproduce reference predicate exactly
            const float q = __fdiv_rn(d2, qden);
            if (q <= 0.105340f)       keep = true;
            else if (q >= 0.105380f)  keep = false;
            else                      keep = ((float)exp(-(double)q) >= 0.9f);
            keep = keep && (d2 > 0.0f) && ((i_base + ii) != j);
        }

        unsigned m = __ballot_sync(0xffffffffu, keep);
        if (m) {
            float* rowp = out + (size_t)(i_base + ii) * (NPTS * NOUT);
            do {
                const int e0 = __ffs(m) - 1;
                m &= m - 1u;
                const int e1 = m ? (__ffs(m) - 1) : -1;
                if (e1 >= 0) m &= m - 1u;

                const int  src   = (lane < 16) ? e0 : (e1 >= 0 ? e1 : e0);
                const bool valid = (lane < 16) || (e1 >= 0);
                const float d2v  = __shfl_sync(0xffffffffu, d2, src);
                const float v    = __expf(-__fmul_rn(d2v, invc));
                if (valid)
                    rowp[(size_t)(jw + src) * NOUT + c] = v;
            } while (m);
        }
    }
}

extern "C" void kernel_launch(void* const* d_in, const int* in_sizes, int n_in,
                              void* d_out, int out_size)
{
    const float* coord = (const float*)d_in[0];   // [3072, 3] fp32
    const float* sig   = (const float*)d_in[1];   // [16] fp32
    float* out = (float*)d_out;                   // [1, 3072, 3072, 16] fp32

    const size_t chunk_elems = (size_t)ROWS_PER * NPTS * NOUT;   // floats
    const size_t chunk_bytes = chunk_elems * sizeof(float);

    // Fork a side stream so each chunk's sparse fill overlaps the NEXT
    // chunk's memset. Host-side stream/event creation only happens on the
    // correctness + capture calls (graph replays never re-enter here).
    cudaStream_t s2;
    cudaStreamCreateWithFlags(&s2, cudaStreamNonBlocking);

    dim3 block(TJ);
    dim3 grid(NPTS / TJ, ROWS_PER / TI);   // (12, 12) per chunk

    for (int k = 0; k < NCHUNK; k++) {
        // memset chunk k on the main (capture-origin) stream
        cudaMemsetAsync((char*)d_out + (size_t)k * chunk_bytes, 0, chunk_bytes, 0);

        cudaEvent_t ev;
        cudaEventCreateWithFlags(&ev, cudaEventDisableTiming);
        cudaEventRecord(ev, 0);
        cudaStreamWaitEvent(s2, ev, 0);

        // fill chunk k on the side stream (overlaps memset of chunk k+1)
        sparse_fill_kernel<<<grid, block, 0, s2>>>(coord, sig, out, k * ROWS_PER);

        cudaEventDestroy(ev);   // node already captured; handle no longer needed
    }

    // Join the side stream back into the origin stream.
    cudaEvent_t evj;
    cudaEventCreateWithFlags(&evj, cudaEventDisableTiming);
    cudaEventRecord(evj, s2);
    cudaStreamWaitEvent(0, evj, 0);
    cudaEventDestroy(evj);
    cudaStreamDestroy(s2);
}

// round 7
// speedup vs baseline: 1.0587x; 1.0587x over previous
#include <cuda_runtime.h>
#include <math.h>

#define NPTS 3072
#define NOUT 16
#define TI 32            // i-rows per block
#define TJ 256           // j-cols per block (= blockDim.x)
#define SCAP 1280        // per-block smem edge capacity
#define GCAP (1 << 20)   // global edge-list capacity (~3.6x expected count)

// Static scratch (no allocation allowed): global edge list.
__device__ unsigned g_cnt;
__device__ unsigned g_eidx[GCAP];
__device__ float    g_ed2[GCAP];

__global__ void reset_kernel() { g_cnt = 0u; }

// Phase A (concurrent with memset, never touches d_out):
// find kept edges, compact per-block in smem, flush to global list.
__global__ __launch_bounds__(256) void edge_find_kernel(
    const float* __restrict__ coord,
    const float* __restrict__ sig)
{
    __shared__ float4   s_i[TI];        // xi, yi, zi, sqi
    __shared__ float    s_qden, s_lo, s_hi;
    __shared__ unsigned s_cnt, s_base;
    __shared__ unsigned s_idx[SCAP];
    __shared__ float    s_d2[SCAP];

    const int tid    = threadIdx.x;
    const int j_base = blockIdx.x * TJ;
    const int i_base = blockIdx.y * TI;
    const int j      = j_base + tid;

    if (tid == 0) {
        float sm = sig[NOUT - 1];
        float qd = __fmul_rn(__fmul_rn(2.0f, sm), sm);
        s_qden = qd;
        s_lo = 0.105300f * qd;   // conservative fast-keep bound
        s_hi = 0.105420f * qd;   // conservative fast-drop bound
        s_cnt = 0u;
    }
    if (tid < TI) {
        int ig = i_base + tid;
        float x = coord[3 * ig + 0];
        float y = coord[3 * ig + 1];
        float z = coord[3 * ig + 2];
        float sq = __fadd_rn(__fadd_rn(__fmul_rn(x, x), __fmul_rn(y, y)),
                             __fmul_rn(z, z));
        s_i[tid] = make_float4(x, y, z, sq);
    }

    const float xj = coord[3 * j + 0];
    const float yj = coord[3 * j + 1];
    const float zj = coord[3 * j + 2];
    const float sqj = __fadd_rn(__fadd_rn(__fmul_rn(xj, xj), __fmul_rn(yj, yj)),
                                __fmul_rn(zj, zj));
    __syncthreads();

    const float lo = s_lo, hi = s_hi, qden = s_qden;

#pragma unroll 4
    for (int ii = 0; ii < TI; ii++) {
        const float4 I = s_i[ii];
        const float dot = __fmaf_rn(I.z, zj, __fmaf_rn(I.y, yj, __fmul_rn(I.x, xj)));
        float d2 = __fsub_rn(__fadd_rn(I.w, sqj), __fmul_rn(2.0f, dot));
        d2 = fmaxf(d2, 0.0f);

        bool keep;
        if (d2 <= lo) {
            keep = (d2 > 0.0f) && ((i_base + ii) != j);
        } else if (d2 >= hi) {
            keep = false;
        } else {
            // boundary band: reproduce reference predicate exactly
            const float q = __fdiv_rn(d2, qden);
            if (q <= 0.105340f)       keep = true;
            else if (q >= 0.105380f)  keep = false;
            else                      keep = ((float)exp(-(double)q) >= 0.9f);
            keep = keep && (d2 > 0.0f) && ((i_base + ii) != j);
        }

        if (keep) {
            const unsigned pidx = ((unsigned)(i_base + ii) << 12) | (unsigned)j;
            unsigned slot = atomicAdd(&s_cnt, 1u);
            if (slot < SCAP) {
                s_idx[slot] = pidx;
                s_d2[slot]  = d2;
            } else {                      // ~unreachable overflow path
                unsigned g = atomicAdd(&g_cnt, 1u);
                if (g < GCAP) { g_eidx[g] = pidx; g_ed2[g] = d2; }
            }
        }
    }
    __syncthreads();

    const unsigned cnt = min(s_cnt, (unsigned)SCAP);
    if (tid == 0) s_base = atomicAdd(&g_cnt, cnt);
    __syncthreads();
    const unsigned base = s_base;
    for (unsigned e = tid; e < cnt; e += TJ) {
        g_eidx[base + e] = s_idx[e];
        g_ed2[base + e]  = s_d2[e];
    }
}

// Phase B (after memset AND edge_find): dense 16-lanes-per-edge scatter.
__global__ __launch_bounds__(256) void scatter_kernel(
    const float* __restrict__ sig,
    float* __restrict__ out)
{
    const int c = threadIdx.x & (NOUT - 1);
    const float s = sig[c];
    const float invc = __fdiv_rn(1.0f, __fmul_rn(__fmul_rn(2.0f, s), s));

    const unsigned n      = g_cnt;
    unsigned       e      = (blockIdx.x * blockDim.x + threadIdx.x) >> 4;
    const unsigned stride = (gridDim.x * blockDim.x) >> 4;

    for (; e < n; e += stride) {
        const unsigned p  = g_eidx[e];
        const float    d2 = g_ed2[e];
        const unsigned i  = p >> 12;
        const unsigned j  = p & 4095u;
        out[((size_t)i * NPTS + j) * NOUT + c] = __expf(-__fmul_rn(d2, invc));
    }
}

extern "C" void kernel_launch(void* const* d_in, const int* in_sizes, int n_in,
                              void* d_out, int out_size)
{
    const float* coord = (const float*)d_in[0];   // [3072, 3] fp32
    const float* sig   = (const float*)d_in[1];   // [16] fp32
    float* out = (float*)d_out;                   // [1, 3072, 3072, 16] fp32

    cudaStream_t s2;
    cudaStreamCreateWithFlags(&s2, cudaStreamNonBlocking);

    // Fork side stream from the capture-origin stream.
    cudaEvent_t ev0, ev1;
    cudaEventCreateWithFlags(&ev0, cudaEventDisableTiming);
    cudaEventCreateWithFlags(&ev1, cudaEventDisableTiming);
    cudaEventRecord(ev0, 0);
    cudaStreamWaitEvent(s2, ev0, 0);

    // Side stream: reset counter, find edges (never touches d_out).
    reset_kernel<<<1, 1, 0, s2>>>();
    dim3 block(TJ);
    dim3 grid(NPTS / TJ, NPTS / TI);   // (12, 96)
    edge_find_kernel<<<grid, block, 0, s2>>>(coord, sig);
    cudaEventRecord(ev1, s2);

    // Main stream: bulk zeros at the HBM write roofline (concurrent with above).
    cudaMemsetAsync(d_out, 0, (size_t)NPTS * NPTS * NOUT * sizeof(float), 0);

    // Join, then scatter the kept values on top of the zeros.
    cudaStreamWaitEvent(0, ev1, 0);
    scatter_kernel<<<2048, 256, 0, 0>>>(sig, out);

    cudaEventDestroy(ev0);
    cudaEventDestroy(ev1);
    cudaStreamDestroy(s2);
}

// round 8
// speedup vs baseline: 1.1570x; 1.0928x over previous
#include <cuda_runtime.h>
#include <math.h>

#define NPTS 3072
#define NOUT 16
#define TI 32          // i-rows per block
#define TJ 256         // j-cols per block (= blockDim.x)

// Symmetric sparse fill: process only i<j pairs; each keeper writes BOTH
// out[i,j,:] and out[j,i,:] (d2 and the predicate are bit-exactly symmetric).
// Bulk zeros come from the cudaMemsetAsync node (HBM write roofline).
__global__ __launch_bounds__(256) void sparse_fill_sym_kernel(
    const float* __restrict__ coord,
    const float* __restrict__ sig,
    float* __restrict__ out)
{
    const int j_base = blockIdx.x * TJ;
    const int i_base = blockIdx.y * TI;
    // Tile entirely at i >= j: mirror of an i<j tile, nothing to do.
    if (i_base >= j_base + TJ) return;

    __shared__ float4 s_i[TI];          // xi, yi, zi, sqi
    __shared__ float  s_inv[NOUT];      // 1/(2*sigma_c^2), reference rounding
    __shared__ float  s_qden, s_lo, s_hi;

    const int tid  = threadIdx.x;
    const int lane = tid & 31;
    const int j    = j_base + tid;
    const int jw   = j_base + (tid & ~31);   // warp's j origin

    if (tid < NOUT) {
        float s = sig[tid];
        s_inv[tid] = __fdiv_rn(1.0f, __fmul_rn(__fmul_rn(2.0f, s), s));
    }
    if (tid == 0) {
        float sm = sig[NOUT - 1];
        float qd = __fmul_rn(__fmul_rn(2.0f, sm), sm);
        s_qden = qd;
        s_lo = 0.105300f * qd;   // conservative fast-keep bound
        s_hi = 0.105420f * qd;   // conservative fast-drop bound
    }
    if (tid < TI) {
        int ig = i_base + tid;
        float x = coord[3 * ig + 0];
        float y = coord[3 * ig + 1];
        float z = coord[3 * ig + 2];
        float sq = __fadd_rn(__fadd_rn(__fmul_rn(x, x), __fmul_rn(y, y)),
                             __fmul_rn(z, z));
        s_i[tid] = make_float4(x, y, z, sq);
    }

    // j-coords register-resident across the whole i-loop
    const float xj = coord[3 * j + 0];
    const float yj = coord[3 * j + 1];
    const float zj = coord[3 * j + 2];
    const float sqj = __fadd_rn(__fadd_rn(__fmul_rn(xj, xj), __fmul_rn(yj, yj)),
                                __fmul_rn(zj, zj));
    __syncthreads();

    const float lo = s_lo, hi = s_hi, qden = s_qden;
    const int   c    = lane & (NOUT - 1);      // my output channel
    const float invc = s_inv[c];
    const bool  hi_half = (lane >= 16);        // lanes 16-31 write the mirror

    for (int ii = 0; ii < TI; ii++) {
        const int ig = i_base + ii;
        const float4 I = s_i[ii];
        const float dot = __fmaf_rn(I.z, zj, __fmaf_rn(I.y, yj, __fmul_rn(I.x, xj)));
        float d2 = __fsub_rn(__fadd_rn(I.w, sqj), __fmul_rn(2.0f, dot));
        d2 = fmaxf(d2, 0.0f);

        bool keep;
        if (d2 <= lo) {
            keep = (d2 > 0.0f) && (ig < j);
        } else if (d2 >= hi) {
            keep = false;
        } else {
            // boundary band: reproduce reference predicate exactly
            const float q = __fdiv_rn(d2, qden);
            if (q <= 0.105340f)       keep = true;
            else if (q >= 0.105380f)  keep = false;
            else                      keep = ((float)exp(-(double)q) >= 0.9f);
            keep = keep && (d2 > 0.0f) && (ig < j);
        }

        unsigned m = __ballot_sync(0xffffffffu, keep);
        while (m) {
            const int src = __ffs(m) - 1;
            m &= m - 1u;
            const float d2v = __shfl_sync(0xffffffffu, d2, src);
            const int   js  = jw + src;
            const float v   = __expf(-__fmul_rn(d2v, invc));
            // lanes 0-15: row (ig, js); lanes 16-31: mirror row (js, ig)
            const size_t pair = hi_half ? ((size_t)js * NPTS + ig)
                                        : ((size_t)ig * NPTS + js);
            out[pair * NOUT + c] = v;
        }
    }
}

extern "C" void kernel_launch(void* const* d_in, const int* in_sizes, int n_in,
                              void* d_out, int out_size)
{
    const float* coord = (const float*)d_in[0];   // [3072, 3] fp32
    const float* sig   = (const float*)d_in[1];   // [16] fp32
    float* out = (float*)d_out;                   // [1, 3072, 3072, 16] fp32

    // Bulk zeros at the HBM write roofline (graph memset node).
    cudaMemsetAsync(d_out, 0, (size_t)NPTS * NPTS * NOUT * sizeof(float), 0);

    dim3 block(TJ);
    dim3 grid(NPTS / TJ, NPTS / TI);   // (12, 96); ~46% of tiles exit instantly
    sparse_fill_sym_kernel<<<grid, block>>>(coord, sig, out);
}